// round 9
// baseline (speedup 1.0000x reference)
#include <cuda_runtime.h>
#include <cstdint>
#include <math.h>

#define CH 512
#define NG 64
#define N_SAMP 16
#define H 64
#define W 64
#define HW 4096

#define SROWS 66
#define SCOLS 72                          // interior at col 4 -> 16B-aligned
#define CHT   (SROWS * SCOLS)             // 4752 floats
#define STILE (8 * CHT)                   // 38016 floats = 152064 B

__device__ __forceinline__ void cp_async16(uint32_t dst, const void* src) {
    asm volatile("cp.async.cg.shared.global [%0], [%1], 16;"
                 :: "r"(dst), "l"(src));
}

// ===========================================================================
// ONE fused kernel. Grid (64, 16) x 512 threads.
//  1. issue cp.async for the whole content tile (overlaps everything below)
//  2. halo columns via regular LDG/STS
//  3. prep: style -> smem, d (warp-per-output), bias, S  (no reg arrays)
//  4. wait cp.async; instance-norm stats from smem
//  5. conv + pointwise collapse + norm + multiply, float4 streaming stores
// ===========================================================================
__global__ void __launch_bounds__(512) fused_kernel(
    const float* __restrict__ content,
    const float* __restrict__ style,
    const float* __restrict__ dw_w,
    const float* __restrict__ dw_b,
    const float* __restrict__ pk_w,
    const float* __restrict__ pk_b,
    const float* __restrict__ pb_w,
    const float* __restrict__ pb_b,
    float* __restrict__ out)
{
    extern __shared__ float s[];          // [8][SROWS][SCOLS] content tile
    __shared__ float st[8192];            // style [512][16]
    __shared__ float sd[512];             // style spatial mean
    __shared__ float fd[72];
    __shared__ float fb[8], fm[8], fr[8];
    __shared__ float red[32];
    __shared__ float fS_sh;

    int g = blockIdx.x;
    int n = blockIdx.y;
    int tid = threadIdx.x;
    int lane = tid & 31, warp = tid >> 5;
    int cbase = n * 512 + g * 8;

    // ============ 1. content tile -> smem via cp.async (interior cols) =====
    {
        int c    = warp >> 1;
        int half = warp & 1;
        const float* bc = content + (size_t)(cbase + c) * HW;
        uint32_t sc = (uint32_t)__cvta_generic_to_shared(s + c * CHT);
        // 33 rows x 16 float4 = 528 segs per half-channel, 32 lanes
        #pragma unroll
        for (int i = 0; i < 17; i++) {
            int seg = i * 32 + lane;
            if (seg < 528) {
                int lr = half * 33 + (seg >> 4);                   // 0..65
                int k  = seg & 15;
                int gr = (lr == 0) ? 1 : (lr == 65 ? 62 : lr - 1); // reflect
                cp_async16(sc + (uint32_t)(lr * SCOLS + 4 + 4 * k) * 4u,
                           bc + gr * W + 4 * k);
            }
        }
        asm volatile("cp.async.commit_group;" ::: "memory");
    }

    // ============ 2. halo columns (regular) ================================
    for (int idx = tid; idx < 8 * SROWS; idx += 512) {
        int c2 = idx / SROWS, lr = idx % SROWS;
        int gr = (lr == 0) ? 1 : (lr == 65 ? 62 : lr - 1);
        const float* b2 = content + (size_t)(cbase + c2) * HW + gr * W;
        float* row = s + c2 * CHT + lr * SCOLS;
        row[3]  = b2[1];
        row[68] = b2[62];
    }

    // ============ 3. prep ==================================================
    // stage style [512][16]
    {
        const float4* sp = (const float4*)(style + (size_t)n * 8192);
        #pragma unroll
        for (int i = 0; i < 4; i++)
            ((float4*)st)[tid + 512 * i] = sp[tid + 512 * i];
    }
    __syncthreads();
    {   // sd[c] = mean over 4x4
        float a = 0.f;
        #pragma unroll
        for (int p = 0; p < 16; p++) a += st[tid * 16 + p];
        sd[tid] = a * (1.f / 16.f);
    }
    __syncthreads();

    // d: warp-per-output, o = warp + 16*k
    {
        const float4* w4base = (const float4*)dw_w;
        #pragma unroll
        for (int k = 0; k < 5; k++) {
            int o = warp + 16 * k;
            if (o < 72) {
                int j = o / 9, pos = o % 9;
                int ky = pos / 3, kx = pos % 3;
                float acc = 0.f;
                #pragma unroll
                for (int k16 = 0; k16 < 16; k16++) {
                    int c = lane + 32 * k16;
                    float4 w = w4base[j * 512 + c];
                    const float* pb = st + c * 16 + ky * 4 + kx;
                    acc += w.x * pb[0] + w.y * pb[1]
                         + w.z * pb[4] + w.w * pb[5];
                }
                #pragma unroll
                for (int off = 16; off; off >>= 1)
                    acc += __shfl_down_sync(0xffffffffu, acc, off);
                if (lane == 0) {
                    float v = acc + dw_b[j];
                    fd[o] = v >= 0.f ? v : 0.01f * v;
                }
            }
        }
    }
    // bias (warps 0-7) and S (warp 8)
    if (warp < 8) {
        const float* row = pb_w + (size_t)(g * 8 + warp) * 512;
        float acc = 0.f;
        #pragma unroll
        for (int k = 0; k < 16; k++) {
            int c2 = lane + 32 * k;
            acc += row[c2] * sd[c2];
        }
        #pragma unroll
        for (int off = 16; off; off >>= 1)
            acc += __shfl_down_sync(0xffffffffu, acc, off);
        if (lane == 0) fb[warp] = acc + pb_b[g * 8 + warp];
    } else if (warp == 8) {
        float acc = 0.f;
        #pragma unroll
        for (int k = 0; k < 16; k++) {
            int c2 = lane + 32 * k;
            float ws = 0.f;
            #pragma unroll
            for (int j = 0; j < 8; j++) ws += pk_w[j * 512 + c2];
            acc += sd[c2] * ws;
        }
        #pragma unroll
        for (int off = 16; off; off >>= 1)
            acc += __shfl_down_sync(0xffffffffu, acc, off);
        if (lane == 0) {
            float bsum = 0.f;
            #pragma unroll
            for (int j = 0; j < 8; j++) bsum += pk_b[j];
            fS_sh = acc + bsum;
        }
    }

    // ============ 4. wait tile; stats from smem ============================
    asm volatile("cp.async.wait_group 0;" ::: "memory");
    __syncthreads();
    {
        int c    = warp >> 1;
        int half = warp & 1;
        const float* sc = s + c * CHT;
        float sum = 0.f, sq = 0.f;
        // interior rows: half0 -> 1..32, half1 -> 33..64; 32 rows x 16 f4
        #pragma unroll
        for (int i = 0; i < 16; i++) {
            int seg = i * 32 + lane;
            int lr = 1 + half * 32 + (seg >> 4);
            int k  = seg & 15;
            float4 v = *(const float4*)(sc + lr * SCOLS + 4 + 4 * k);
            sum += v.x + v.y + v.z + v.w;
            sq  += v.x * v.x + v.y * v.y + v.z * v.z + v.w * v.w;
        }
        #pragma unroll
        for (int off = 16; off; off >>= 1) {
            sum += __shfl_down_sync(0xffffffffu, sum, off);
            sq  += __shfl_down_sync(0xffffffffu, sq,  off);
        }
        if (lane == 0) { red[warp] = sum; red[16 + warp] = sq; }
    }
    __syncthreads();
    if (tid < 8) {
        float S = red[2 * tid] + red[2 * tid + 1];
        float Q = red[16 + 2 * tid] + red[16 + 2 * tid + 1];
        float mean = S * (1.f / HW);
        float var  = (Q - S * S * (1.f / HW)) * (1.f / (HW - 1));  // ddof=1
        fm[tid] = mean;
        fr[tid] = rsqrtf(var + 1e-5f);
    }
    __syncthreads();

    // ============ 5. conv: 2 rows x 4 cols per thread ======================
    int r2 = tid >> 4;                    // 0..31
    int q4 = (tid & 15) * 4;              // output col base
    int h0 = 2 * r2;                      // output rows h0, h0+1

    float D0[4] = {0.f, 0.f, 0.f, 0.f};
    float D1[4] = {0.f, 0.f, 0.f, 0.f};

    #pragma unroll
    for (int j = 0; j < 8; j++) {
        const float* sj = s + j * CHT;
        const float* fj = fd + j * 9;
        #pragma unroll
        for (int rr = 0; rr < 4; rr++) {
            const float* rp = sj + (h0 + rr) * SCOLS + q4;
            float vL = rp[3];
            float4 f4 = *(const float4*)(rp + 4);
            float vR = rp[8];
            if (rr < 3) {
                float a = fj[rr * 3], b2 = fj[rr * 3 + 1], cc = fj[rr * 3 + 2];
                D0[0] += a * vL   + b2 * f4.x + cc * f4.y;
                D0[1] += a * f4.x + b2 * f4.y + cc * f4.z;
                D0[2] += a * f4.y + b2 * f4.z + cc * f4.w;
                D0[3] += a * f4.z + b2 * f4.w + cc * vR;
            }
            if (rr >= 1) {
                int kr = rr - 1;
                float a = fj[kr * 3], b2 = fj[kr * 3 + 1], cc = fj[kr * 3 + 2];
                D1[0] += a * vL   + b2 * f4.x + cc * f4.y;
                D1[1] += a * f4.x + b2 * f4.y + cc * f4.z;
                D1[2] += a * f4.y + b2 * f4.z + cc * f4.w;
                D1[3] += a * f4.z + b2 * f4.w + cc * vR;
            }
        }
    }

    float S = fS_sh;
    float* obase = out + (size_t)cbase * HW + h0 * W + q4;

    #pragma unroll
    for (int o = 0; o < 8; o++) {
        const float* so = s + o * CHT;
        float mo = fm[o], ro = fr[o], bo = fb[o];
        float4 r0v, r1v;
        {
            float4 cen = *(const float4*)(so + (h0 + 1) * SCOLS + 4 + q4);
            float p0 = D0[0] * S + bo, p1 = D0[1] * S + bo;
            float p2 = D0[2] * S + bo, p3 = D0[3] * S + bo;
            p0 = p0 >= 0.f ? p0 : 0.01f * p0;
            p1 = p1 >= 0.f ? p1 : 0.01f * p1;
            p2 = p2 >= 0.f ? p2 : 0.01f * p2;
            p3 = p3 >= 0.f ? p3 : 0.01f * p3;
            r0v.x = (cen.x - mo) * ro * p0;
            r0v.y = (cen.y - mo) * ro * p1;
            r0v.z = (cen.z - mo) * ro * p2;
            r0v.w = (cen.w - mo) * ro * p3;
        }
        {
            float4 cen = *(const float4*)(so + (h0 + 2) * SCOLS + 4 + q4);
            float p0 = D1[0] * S + bo, p1 = D1[1] * S + bo;
            float p2 = D1[2] * S + bo, p3 = D1[3] * S + bo;
            p0 = p0 >= 0.f ? p0 : 0.01f * p0;
            p1 = p1 >= 0.f ? p1 : 0.01f * p1;
            p2 = p2 >= 0.f ? p2 : 0.01f * p2;
            p3 = p3 >= 0.f ? p3 : 0.01f * p3;
            r1v.x = (cen.x - mo) * ro * p0;
            r1v.y = (cen.y - mo) * ro * p1;
            r1v.z = (cen.z - mo) * ro * p2;
            r1v.w = (cen.w - mo) * ro * p3;
        }
        __stcs((float4*)(obase + (size_t)o * HW),     r0v);
        __stcs((float4*)(obase + (size_t)o * HW + W), r1v);
    }
}

// ===========================================================================
extern "C" void kernel_launch(void* const* d_in, const int* in_sizes, int n_in,
                              void* d_out, int out_size)
{
    const float* style   = (const float*)d_in[0];
    const float* content = (const float*)d_in[1];
    const float* dw_w    = (const float*)d_in[2];
    const float* dw_b    = (const float*)d_in[3];
    const float* pk_w    = (const float*)d_in[4];
    const float* pk_b    = (const float*)d_in[5];
    const float* pb_w    = (const float*)d_in[6];
    const float* pb_b    = (const float*)d_in[7];
    float* out = (float*)d_out;

    static bool attr_set = false;
    if (!attr_set) {
        cudaFuncSetAttribute(fused_kernel,
                             cudaFuncAttributeMaxDynamicSharedMemorySize,
                             STILE * sizeof(float));
        attr_set = true;
    }

    fused_kernel<<<dim3(NG, N_SAMP), 512, STILE * sizeof(float)>>>(
        content, style, dw_w, dw_b, pk_w, pk_b, pb_w, pb_b, out);
}

// round 10
// speedup vs baseline: 1.0151x; 1.0151x over previous
#include <cuda_runtime.h>
#include <cstdint>
#include <math.h>

#define CH 512
#define NG 64
#define N_SAMP 16
#define H 64
#define W 64
#define HW 4096

#define SROWS 66
#define SCOLS 72                          // interior at col 4 -> 16B-aligned
#define CHT   (SROWS * SCOLS)             // 4752 floats
#define STILE (8 * CHT)                   // 38016 floats = 152064 B

// ===========================================================================
// ONE fused kernel. Grid (64, 16) x 512 threads.
//  A. prep: style -> smem, d (warp-per-output, spill-free), bias, S
//  B. content tile load via LDG.128 with in-register instance-norm stats
//  C. conv + pointwise collapse + norm + multiply, float4 streaming stores
// ===========================================================================
__global__ void __launch_bounds__(512) fused_kernel(
    const float* __restrict__ content,
    const float* __restrict__ style,
    const float* __restrict__ dw_w,
    const float* __restrict__ dw_b,
    const float* __restrict__ pk_w,
    const float* __restrict__ pk_b,
    const float* __restrict__ pb_w,
    const float* __restrict__ pb_b,
    float* __restrict__ out)
{
    extern __shared__ float s[];          // [8][SROWS][SCOLS] content tile
    __shared__ float st[8192];            // style [512][16]
    __shared__ float sd[512];             // style spatial mean
    __shared__ float fd[72];
    __shared__ float fb[8], fm[8], fr[8];
    __shared__ float red[32];
    __shared__ float fS_sh;

    int g = blockIdx.x;
    int n = blockIdx.y;
    int tid = threadIdx.x;
    int lane = tid & 31, warp = tid >> 5;
    int cbase = n * 512 + g * 8;

    // ============ A. prep ==================================================
    {
        const float4* sp = (const float4*)(style + (size_t)n * 8192);
        #pragma unroll
        for (int i = 0; i < 4; i++)
            ((float4*)st)[tid + 512 * i] = sp[tid + 512 * i];
    }
    __syncthreads();
    {   // sd[c] = mean over 4x4
        float a = 0.f;
        #pragma unroll
        for (int p = 0; p < 16; p++) a += st[tid * 16 + p];
        sd[tid] = a * (1.f / 16.f);
    }
    __syncthreads();

    // d: warp-per-output (o = warp + 16*k), 16 chans per lane, no reg arrays
    {
        const float4* w4base = (const float4*)dw_w;
        #pragma unroll
        for (int k = 0; k < 5; k++) {
            int o = warp + 16 * k;
            if (o < 72) {
                int j = o / 9, pos = o % 9;
                int ky = pos / 3, kx = pos % 3;
                float acc = 0.f;
                #pragma unroll
                for (int k16 = 0; k16 < 16; k16++) {
                    int c = lane + 32 * k16;
                    float4 w = w4base[j * 512 + c];
                    const float* pb = st + c * 16 + ky * 4 + kx;
                    acc += w.x * pb[0] + w.y * pb[1]
                         + w.z * pb[4] + w.w * pb[5];
                }
                #pragma unroll
                for (int off = 16; off; off >>= 1)
                    acc += __shfl_down_sync(0xffffffffu, acc, off);
                if (lane == 0) {
                    float v = acc + dw_b[j];
                    fd[o] = v >= 0.f ? v : 0.01f * v;
                }
            }
        }
    }
    // bias (warps 0-7) and S (warp 8)
    if (warp < 8) {
        const float* row = pb_w + (size_t)(g * 8 + warp) * 512;
        float acc = 0.f;
        #pragma unroll
        for (int k = 0; k < 16; k++) {
            int c2 = lane + 32 * k;
            acc += row[c2] * sd[c2];
        }
        #pragma unroll
        for (int off = 16; off; off >>= 1)
            acc += __shfl_down_sync(0xffffffffu, acc, off);
        if (lane == 0) fb[warp] = acc + pb_b[g * 8 + warp];
    } else if (warp == 8) {
        float acc = 0.f;
        #pragma unroll
        for (int k = 0; k < 16; k++) {
            int c2 = lane + 32 * k;
            float ws = 0.f;
            #pragma unroll
            for (int j = 0; j < 8; j++) ws += pk_w[j * 512 + c2];
            acc += sd[c2] * ws;
        }
        #pragma unroll
        for (int off = 16; off; off >>= 1)
            acc += __shfl_down_sync(0xffffffffu, acc, off);
        if (lane == 0) {
            float bsum = 0.f;
            #pragma unroll
            for (int j = 0; j < 8; j++) bsum += pk_b[j];
            fS_sh = acc + bsum;
        }
    }
    // fd/fb/fS consumed only after the __syncthreads below

    // ============ B. content tile load, stats in registers =================
    {
        int c    = warp >> 1;
        int half = warp & 1;
        const float* bc = content + (size_t)(cbase + c) * HW;
        float* sc = s + c * CHT;
        float sum = 0.f, sq = 0.f;
        int sub = lane >> 4, q = lane & 15;
        #pragma unroll
        for (int i = 0; i < 17; i++) {
            int rr = 2 * i + sub;
            if (rr < 33) {
                int lr = half * 33 + rr;                           // 0..65
                int gr = (lr == 0) ? 1 : (lr == 65 ? 62 : lr - 1); // reflect
                float4 v = *(const float4*)(bc + gr * W + 4 * q);
                *(float4*)(sc + lr * SCOLS + 4 + 4 * q) = v;       // STS.128
                if (lr >= 1 && lr <= 64) {                         // interior
                    sum += v.x + v.y + v.z + v.w;
                    sq  += v.x * v.x + v.y * v.y + v.z * v.z + v.w * v.w;
                }
            }
        }
        // halo columns: col 3 <- global col 1 ; col 68 <- global col 62
        for (int idx = tid; idx < 8 * SROWS; idx += 512) {
            int c2 = idx / SROWS, lr = idx % SROWS;
            int gr = (lr == 0) ? 1 : (lr == 65 ? 62 : lr - 1);
            const float* b2 = content + (size_t)(cbase + c2) * HW + gr * W;
            float* row = s + c2 * CHT + lr * SCOLS;
            row[3]  = b2[1];
            row[68] = b2[62];
        }
        #pragma unroll
        for (int off = 16; off; off >>= 1) {
            sum += __shfl_down_sync(0xffffffffu, sum, off);
            sq  += __shfl_down_sync(0xffffffffu, sq,  off);
        }
        if (lane == 0) { red[warp] = sum; red[16 + warp] = sq; }
    }
    __syncthreads();
    if (tid < 8) {
        float S = red[2 * tid] + red[2 * tid + 1];
        float Q = red[16 + 2 * tid] + red[16 + 2 * tid + 1];
        float mean = S * (1.f / HW);
        float var  = (Q - S * S * (1.f / HW)) * (1.f / (HW - 1));  // ddof=1
        fm[tid] = mean;
        fr[tid] = rsqrtf(var + 1e-5f);
    }
    __syncthreads();

    // ============ C. conv: 2 rows x 4 cols per thread ======================
    int r2 = tid >> 4;                    // 0..31
    int q4 = (tid & 15) * 4;              // output col base
    int h0 = 2 * r2;                      // output rows h0, h0+1

    float D0[4] = {0.f, 0.f, 0.f, 0.f};
    float D1[4] = {0.f, 0.f, 0.f, 0.f};

    #pragma unroll
    for (int j = 0; j < 8; j++) {
        const float* sj = s + j * CHT;
        const float* fj = fd + j * 9;
        #pragma unroll
        for (int rr = 0; rr < 4; rr++) {
            const float* rp = sj + (h0 + rr) * SCOLS + q4;
            float vL = rp[3];
            float4 f4 = *(const float4*)(rp + 4);   // aligned LDS.128
            float vR = rp[8];
            if (rr < 3) {
                float a = fj[rr * 3], b2 = fj[rr * 3 + 1], cc = fj[rr * 3 + 2];
                D0[0] += a * vL   + b2 * f4.x + cc * f4.y;
                D0[1] += a * f4.x + b2 * f4.y + cc * f4.z;
                D0[2] += a * f4.y + b2 * f4.z + cc * f4.w;
                D0[3] += a * f4.z + b2 * f4.w + cc * vR;
            }
            if (rr >= 1) {
                int kr = rr - 1;
                float a = fj[kr * 3], b2 = fj[kr * 3 + 1], cc = fj[kr * 3 + 2];
                D1[0] += a * vL   + b2 * f4.x + cc * f4.y;
                D1[1] += a * f4.x + b2 * f4.y + cc * f4.z;
                D1[2] += a * f4.y + b2 * f4.z + cc * f4.w;
                D1[3] += a * f4.z + b2 * f4.w + cc * vR;
            }
        }
    }

    float S = fS_sh;
    float* obase = out + (size_t)cbase * HW + h0 * W + q4;

    #pragma unroll
    for (int o = 0; o < 8; o++) {
        const float* so = s + o * CHT;
        float mo = fm[o], ro = fr[o], bo = fb[o];
        float4 r0v, r1v;
        {
            float4 cen = *(const float4*)(so + (h0 + 1) * SCOLS + 4 + q4);
            float p0 = D0[0] * S + bo, p1 = D0[1] * S + bo;
            float p2 = D0[2] * S + bo, p3 = D0[3] * S + bo;
            p0 = p0 >= 0.f ? p0 : 0.01f * p0;
            p1 = p1 >= 0.f ? p1 : 0.01f * p1;
            p2 = p2 >= 0.f ? p2 : 0.01f * p2;
            p3 = p3 >= 0.f ? p3 : 0.01f * p3;
            r0v.x = (cen.x - mo) * ro * p0;
            r0v.y = (cen.y - mo) * ro * p1;
            r0v.z = (cen.z - mo) * ro * p2;
            r0v.w = (cen.w - mo) * ro * p3;
        }
        {
            float4 cen = *(const float4*)(so + (h0 + 2) * SCOLS + 4 + q4);
            float p0 = D1[0] * S + bo, p1 = D1[1] * S + bo;
            float p2 = D1[2] * S + bo, p3 = D1[3] * S + bo;
            p0 = p0 >= 0.f ? p0 : 0.01f * p0;
            p1 = p1 >= 0.f ? p1 : 0.01f * p1;
            p2 = p2 >= 0.f ? p2 : 0.01f * p2;
            p3 = p3 >= 0.f ? p3 : 0.01f * p3;
            r1v.x = (cen.x - mo) * ro * p0;
            r1v.y = (cen.y - mo) * ro * p1;
            r1v.z = (cen.z - mo) * ro * p2;
            r1v.w = (cen.w - mo) * ro * p3;
        }
        __stcs((float4*)(obase + (size_t)o * HW),     r0v);
        __stcs((float4*)(obase + (size_t)o * HW + W), r1v);
    }
}

// ===========================================================================
extern "C" void kernel_launch(void* const* d_in, const int* in_sizes, int n_in,
                              void* d_out, int out_size)
{
    const float* style   = (const float*)d_in[0];
    const float* content = (const float*)d_in[1];
    const float* dw_w    = (const float*)d_in[2];
    const float* dw_b    = (const float*)d_in[3];
    const float* pk_w    = (const float*)d_in[4];
    const float* pk_b    = (const float*)d_in[5];
    const float* pb_w    = (const float*)d_in[6];
    const float* pb_b    = (const float*)d_in[7];
    float* out = (float*)d_out;

    static bool attr_set = false;
    if (!attr_set) {
        cudaFuncSetAttribute(fused_kernel,
                             cudaFuncAttributeMaxDynamicSharedMemorySize,
                             STILE * sizeof(float));
        attr_set = true;
    }

    fused_kernel<<<dim3(NG, N_SAMP), 512, STILE * sizeof(float)>>>(
        content, style, dw_w, dw_b, pk_w, pk_b, pb_w, pb_b, out);
}

// round 11
// speedup vs baseline: 2.8153x; 2.7734x over previous
#include <cuda_runtime.h>
#include <cstdint>
#include <math.h>

#define CH 512
#define NG 64
#define N_SAMP 16
#define H 64
#define W 64
#define HW 4096

#define SROWS 66
#define SCOLS 72                          // interior at col 4 -> 16B-aligned
#define CHT   (SROWS * SCOLS)             // 4752 floats
#define STILE (8 * CHT)                   // 38016 floats = 152064 B

// ===========================================================================
// ONE fused kernel. Grid (64, 16) x 512 threads.
//  A. prep: style -> smem TRANSPOSED [16][512] (conflict-free),
//     d warp-per-output, bias, S
//  B. content tile load via LDG.128 with in-register instance-norm stats
//  C. conv + pointwise collapse + norm + multiply, float4 streaming stores
// ===========================================================================
__global__ void __launch_bounds__(512) fused_kernel(
    const float* __restrict__ content,
    const float* __restrict__ style,
    const float* __restrict__ dw_w,
    const float* __restrict__ dw_b,
    const float* __restrict__ pk_w,
    const float* __restrict__ pk_b,
    const float* __restrict__ pb_w,
    const float* __restrict__ pb_b,
    float* __restrict__ out)
{
    extern __shared__ float s[];          // [8][SROWS][SCOLS] content tile
    __shared__ float st[16 * 512];        // style TRANSPOSED [pos][channel]
    __shared__ float sd[512];             // style spatial mean
    __shared__ float fd[72];
    __shared__ float fb[8], fm[8], fr[8];
    __shared__ float red[32];
    __shared__ float fS_sh;

    int g = blockIdx.x;
    int n = blockIdx.y;
    int tid = threadIdx.x;
    int lane = tid & 31, warp = tid >> 5;
    int cbase = n * 512 + g * 8;

    // ============ A. prep ==================================================
    // stage style transposed: thread tid = channel, 16 positions
    {
        const float4* sp = (const float4*)(style + (size_t)(n * 512 + tid) * 16);
        float4 a0 = sp[0], a1 = sp[1], a2 = sp[2], a3 = sp[3];
        st[ 0 * 512 + tid] = a0.x;  st[ 1 * 512 + tid] = a0.y;
        st[ 2 * 512 + tid] = a0.z;  st[ 3 * 512 + tid] = a0.w;
        st[ 4 * 512 + tid] = a1.x;  st[ 5 * 512 + tid] = a1.y;
        st[ 6 * 512 + tid] = a1.z;  st[ 7 * 512 + tid] = a1.w;
        st[ 8 * 512 + tid] = a2.x;  st[ 9 * 512 + tid] = a2.y;
        st[10 * 512 + tid] = a2.z;  st[11 * 512 + tid] = a2.w;
        st[12 * 512 + tid] = a3.x;  st[13 * 512 + tid] = a3.y;
        st[14 * 512 + tid] = a3.z;  st[15 * 512 + tid] = a3.w;
        float tot = a0.x + a0.y + a0.z + a0.w + a1.x + a1.y + a1.z + a1.w
                  + a2.x + a2.y + a2.z + a2.w + a3.x + a3.y + a3.z + a3.w;
        sd[tid] = tot * (1.f / 16.f);
    }
    __syncthreads();

    // d: warp-per-output (o = warp + 16*k); all smem reads stride-1 per lane
    {
        const float4* w4base = (const float4*)dw_w;
        #pragma unroll
        for (int k = 0; k < 5; k++) {
            int o = warp + 16 * k;
            if (o < 72) {
                int j = o / 9, pos = o % 9;
                int ky = pos / 3, kx = pos % 3;
                const float* p00 = st + (ky * 4 + kx) * 512;
                const float* p01 = st + (ky * 4 + kx + 1) * 512;
                const float* p10 = st + (ky * 4 + kx + 4) * 512;
                const float* p11 = st + (ky * 4 + kx + 5) * 512;
                float acc = 0.f;
                #pragma unroll
                for (int k16 = 0; k16 < 16; k16++) {
                    int c = lane + 32 * k16;
                    float4 w = w4base[j * 512 + c];
                    acc += w.x * p00[c] + w.y * p01[c]
                         + w.z * p10[c] + w.w * p11[c];
                }
                #pragma unroll
                for (int off = 16; off; off >>= 1)
                    acc += __shfl_down_sync(0xffffffffu, acc, off);
                if (lane == 0) {
                    float v = acc + dw_b[j];
                    fd[o] = v >= 0.f ? v : 0.01f * v;
                }
            }
        }
    }
    // bias (warps 0-7) and S (warp 8)
    if (warp < 8) {
        const float* row = pb_w + (size_t)(g * 8 + warp) * 512;
        float acc = 0.f;
        #pragma unroll
        for (int k = 0; k < 16; k++) {
            int c2 = lane + 32 * k;
            acc += row[c2] * sd[c2];
        }
        #pragma unroll
        for (int off = 16; off; off >>= 1)
            acc += __shfl_down_sync(0xffffffffu, acc, off);
        if (lane == 0) fb[warp] = acc + pb_b[g * 8 + warp];
    } else if (warp == 8) {
        float acc = 0.f;
        #pragma unroll
        for (int k = 0; k < 16; k++) {
            int c2 = lane + 32 * k;
            float ws = 0.f;
            #pragma unroll
            for (int j = 0; j < 8; j++) ws += pk_w[j * 512 + c2];
            acc += sd[c2] * ws;
        }
        #pragma unroll
        for (int off = 16; off; off >>= 1)
            acc += __shfl_down_sync(0xffffffffu, acc, off);
        if (lane == 0) {
            float bsum = 0.f;
            #pragma unroll
            for (int j = 0; j < 8; j++) bsum += pk_b[j];
            fS_sh = acc + bsum;
        }
    }
    // fd/fb/fS consumed only after the __syncthreads below

    // ============ B. content tile load, stats in registers =================
    {
        int c    = warp >> 1;
        int half = warp & 1;
        const float* bc = content + (size_t)(cbase + c) * HW;
        float* sc = s + c * CHT;
        float sum = 0.f, sq = 0.f;
        int sub = lane >> 4, q = lane & 15;
        #pragma unroll
        for (int i = 0; i < 17; i++) {
            int rr = 2 * i + sub;
            if (rr < 33) {
                int lr = half * 33 + rr;                           // 0..65
                int gr = (lr == 0) ? 1 : (lr == 65 ? 62 : lr - 1); // reflect
                float4 v = *(const float4*)(bc + gr * W + 4 * q);
                *(float4*)(sc + lr * SCOLS + 4 + 4 * q) = v;       // STS.128
                if (lr >= 1 && lr <= 64) {                         // interior
                    sum += v.x + v.y + v.z + v.w;
                    sq  += v.x * v.x + v.y * v.y + v.z * v.z + v.w * v.w;
                }
            }
        }
        // halo columns: col 3 <- global col 1 ; col 68 <- global col 62
        for (int idx = tid; idx < 8 * SROWS; idx += 512) {
            int c2 = idx / SROWS, lr = idx % SROWS;
            int gr = (lr == 0) ? 1 : (lr == 65 ? 62 : lr - 1);
            const float* b2 = content + (size_t)(cbase + c2) * HW + gr * W;
            float* row = s + c2 * CHT + lr * SCOLS;
            row[3]  = b2[1];
            row[68] = b2[62];
        }
        #pragma unroll
        for (int off = 16; off; off >>= 1) {
            sum += __shfl_down_sync(0xffffffffu, sum, off);
            sq  += __shfl_down_sync(0xffffffffu, sq,  off);
        }
        if (lane == 0) { red[warp] = sum; red[16 + warp] = sq; }
    }
    __syncthreads();
    if (tid < 8) {
        float S = red[2 * tid] + red[2 * tid + 1];
        float Q = red[16 + 2 * tid] + red[16 + 2 * tid + 1];
        float mean = S * (1.f / HW);
        float var  = (Q - S * S * (1.f / HW)) * (1.f / (HW - 1));  // ddof=1
        fm[tid] = mean;
        fr[tid] = rsqrtf(var + 1e-5f);
    }
    __syncthreads();

    // ============ C. conv: 2 rows x 4 cols per thread ======================
    int r2 = tid >> 4;                    // 0..31
    int q4 = (tid & 15) * 4;              // output col base
    int h0 = 2 * r2;                      // output rows h0, h0+1

    float D0[4] = {0.f, 0.f, 0.f, 0.f};
    float D1[4] = {0.f, 0.f, 0.f, 0.f};

    #pragma unroll
    for (int j = 0; j < 8; j++) {
        const float* sj = s + j * CHT;
        const float* fj = fd + j * 9;
        #pragma unroll
        for (int rr = 0; rr < 4; rr++) {
            const float* rp = sj + (h0 + rr) * SCOLS + q4;
            float vL = rp[3];
            float4 f4 = *(const float4*)(rp + 4);   // aligned LDS.128
            float vR = rp[8];
            if (rr < 3) {
                float a = fj[rr * 3], b2 = fj[rr * 3 + 1], cc = fj[rr * 3 + 2];
                D0[0] += a * vL   + b2 * f4.x + cc * f4.y;
                D0[1] += a * f4.x + b2 * f4.y + cc * f4.z;
                D0[2] += a * f4.y + b2 * f4.z + cc * f4.w;
                D0[3] += a * f4.z + b2 * f4.w + cc * vR;
            }
            if (rr >= 1) {
                int kr = rr - 1;
                float a = fj[kr * 3], b2 = fj[kr * 3 + 1], cc = fj[kr * 3 + 2];
                D1[0] += a * vL   + b2 * f4.x + cc * f4.y;
                D1[1] += a * f4.x + b2 * f4.y + cc * f4.z;
                D1[2] += a * f4.y + b2 * f4.z + cc * f4.w;
                D1[3] += a * f4.z + b2 * f4.w + cc * vR;
            }
        }
    }

    float S = fS_sh;
    float* obase = out + (size_t)cbase * HW + h0 * W + q4;

    #pragma unroll
    for (int o = 0; o < 8; o++) {
        const float* so = s + o * CHT;
        float mo = fm[o], ro = fr[o], bo = fb[o];
        float4 r0v, r1v;
        {
            float4 cen = *(const float4*)(so + (h0 + 1) * SCOLS + 4 + q4);
            float p0 = D0[0] * S + bo, p1 = D0[1] * S + bo;
            float p2 = D0[2] * S + bo, p3 = D0[3] * S + bo;
            p0 = p0 >= 0.f ? p0 : 0.01f * p0;
            p1 = p1 >= 0.f ? p1 : 0.01f * p1;
            p2 = p2 >= 0.f ? p2 : 0.01f * p2;
            p3 = p3 >= 0.f ? p3 : 0.01f * p3;
            r0v.x = (cen.x - mo) * ro * p0;
            r0v.y = (cen.y - mo) * ro * p1;
            r0v.z = (cen.z - mo) * ro * p2;
            r0v.w = (cen.w - mo) * ro * p3;
        }
        {
            float4 cen = *(const float4*)(so + (h0 + 2) * SCOLS + 4 + q4);
            float p0 = D1[0] * S + bo, p1 = D1[1] * S + bo;
            float p2 = D1[2] * S + bo, p3 = D1[3] * S + bo;
            p0 = p0 >= 0.f ? p0 : 0.01f * p0;
            p1 = p1 >= 0.f ? p1 : 0.01f * p1;
            p2 = p2 >= 0.f ? p2 : 0.01f * p2;
            p3 = p3 >= 0.f ? p3 : 0.01f * p3;
            r1v.x = (cen.x - mo) * ro * p0;
            r1v.y = (cen.y - mo) * ro * p1;
            r1v.z = (cen.z - mo) * ro * p2;
            r1v.w = (cen.w - mo) * ro * p3;
        }
        __stcs((float4*)(obase + (size_t)o * HW),     r0v);
        __stcs((float4*)(obase + (size_t)o * HW + W), r1v);
    }
}

// ===========================================================================
extern "C" void kernel_launch(void* const* d_in, const int* in_sizes, int n_in,
                              void* d_out, int out_size)
{
    const float* style   = (const float*)d_in[0];
    const float* content = (const float*)d_in[1];
    const float* dw_w    = (const float*)d_in[2];
    const float* dw_b    = (const float*)d_in[3];
    const float* pk_w    = (const float*)d_in[4];
    const float* pk_b    = (const float*)d_in[5];
    const float* pb_w    = (const float*)d_in[6];
    const float* pb_b    = (const float*)d_in[7];
    float* out = (float*)d_out;

    static bool attr_set = false;
    if (!attr_set) {
        cudaFuncSetAttribute(fused_kernel,
                             cudaFuncAttributeMaxDynamicSharedMemorySize,
                             STILE * sizeof(float));
        attr_set = true;
    }

    fused_kernel<<<dim3(NG, N_SAMP), 512, STILE * sizeof(float)>>>(
        content, style, dw_w, dw_b, pk_w, pk_b, pb_w, pb_b, out);
}

// round 12
// speedup vs baseline: 2.8607x; 1.0161x over previous
#include <cuda_runtime.h>
#include <cstdint>
#include <math.h>

#define CH 512
#define NG 64
#define N_SAMP 16
#define H 64
#define W 64
#define HW 4096

#define SROWS 66
#define SCOLS 72                          // interior at col 4 -> 16B-aligned
#define CHT   (SROWS * SCOLS)             // 4752 floats
#define STILE (8 * CHT)                   // 38016 floats = 152064 B

// ===========================================================================
// ONE fused kernel. Grid (64, 16) x 512 threads, 1 CTA/SM (148KB smem).
//  0. style LDG issued first (latency hidden under content stream)
//  1. content tile load, manually 4-batched LDG.128 for MLP, stats in regs
//  2. prep: transposed style smem (conflict-free), d/bias/S dots
//  3. stats finalize; conv + pointwise collapse + norm + multiply
// ===========================================================================
__global__ void __launch_bounds__(512, 1) fused_kernel(
    const float* __restrict__ content,
    const float* __restrict__ style,
    const float* __restrict__ dw_w,
    const float* __restrict__ dw_b,
    const float* __restrict__ pk_w,
    const float* __restrict__ pk_b,
    const float* __restrict__ pb_w,
    const float* __restrict__ pb_b,
    float* __restrict__ out)
{
    extern __shared__ float s[];          // [8][SROWS][SCOLS] content tile
    __shared__ float st[16 * 512];        // style TRANSPOSED [pos][channel]
    __shared__ float sd[512];             // style spatial mean
    __shared__ float fd[72];
    __shared__ float fb[8], fm[8], fr[8];
    __shared__ float red[32];
    __shared__ float fS_sh;

    int g = blockIdx.x;
    int n = blockIdx.y;
    int tid = threadIdx.x;
    int lane = tid & 31, warp = tid >> 5;
    int cbase = n * 512 + g * 8;

    // ============ 0. style LDG early =======================================
    const float4* sp = (const float4*)(style + (size_t)(n * 512 + tid) * 16);
    float4 a0 = sp[0], a1 = sp[1], a2 = sp[2], a3 = sp[3];

    // ============ 1. content tile load, 4-batched, stats in registers ======
    int c    = warp >> 1;
    int half = warp & 1;
    {
        const float* bc = content + (size_t)(cbase + c) * HW;
        float* sc = s + c * CHT;
        float sum = 0.f, sq = 0.f;
        int sub = lane >> 4, q = lane & 15;

        #pragma unroll
        for (int b = 0; b < 4; b++) {
            int lr0 = half * 33 + (8 * b + sub);
            int lr1 = lr0 + 2, lr2 = lr0 + 4, lr3 = lr0 + 6;
            int gr0 = (lr0 == 0) ? 1 : (lr0 == 65 ? 62 : lr0 - 1);
            int gr1 = (lr1 == 0) ? 1 : (lr1 == 65 ? 62 : lr1 - 1);
            int gr2 = (lr2 == 0) ? 1 : (lr2 == 65 ? 62 : lr2 - 1);
            int gr3 = (lr3 == 0) ? 1 : (lr3 == 65 ? 62 : lr3 - 1);
            float4 v0 = *(const float4*)(bc + gr0 * W + 4 * q);
            float4 v1 = *(const float4*)(bc + gr1 * W + 4 * q);
            float4 v2 = *(const float4*)(bc + gr2 * W + 4 * q);
            float4 v3 = *(const float4*)(bc + gr3 * W + 4 * q);
            *(float4*)(sc + lr0 * SCOLS + 4 + 4 * q) = v0;
            *(float4*)(sc + lr1 * SCOLS + 4 + 4 * q) = v1;
            *(float4*)(sc + lr2 * SCOLS + 4 + 4 * q) = v2;
            *(float4*)(sc + lr3 * SCOLS + 4 + 4 * q) = v3;
            if (lr0 >= 1 && lr0 <= 64) {
                sum += v0.x + v0.y + v0.z + v0.w;
                sq  += v0.x * v0.x + v0.y * v0.y + v0.z * v0.z + v0.w * v0.w;
            }
            sum += v1.x + v1.y + v1.z + v1.w;       // lr1..lr3 always interior
            sq  += v1.x * v1.x + v1.y * v1.y + v1.z * v1.z + v1.w * v1.w;
            sum += v2.x + v2.y + v2.z + v2.w;
            sq  += v2.x * v2.x + v2.y * v2.y + v2.z * v2.z + v2.w * v2.w;
            sum += v3.x + v3.y + v3.z + v3.w;
            sq  += v3.x * v3.x + v3.y * v3.y + v3.z * v3.z + v3.w * v3.w;
        }
        // tail: i=16 (rr=32) exists only for sub==0
        if (sub == 0) {
            int lr = half * 33 + 32;                 // 32 or 65
            int gr = (lr == 65) ? 62 : lr - 1;
            float4 v = *(const float4*)(bc + gr * W + 4 * q);
            *(float4*)(sc + lr * SCOLS + 4 + 4 * q) = v;
            if (lr <= 64) {
                sum += v.x + v.y + v.z + v.w;
                sq  += v.x * v.x + v.y * v.y + v.z * v.z + v.w * v.w;
            }
        }
        // halo columns
        for (int idx = tid; idx < 8 * SROWS; idx += 512) {
            int c2 = idx / SROWS, lr = idx % SROWS;
            int gr = (lr == 0) ? 1 : (lr == 65 ? 62 : lr - 1);
            const float* b2 = content + (size_t)(cbase + c2) * HW + gr * W;
            float* row = s + c2 * CHT + lr * SCOLS;
            row[3]  = b2[1];
            row[68] = b2[62];
        }
        #pragma unroll
        for (int off = 16; off; off >>= 1) {
            sum += __shfl_down_sync(0xffffffffu, sum, off);
            sq  += __shfl_down_sync(0xffffffffu, sq,  off);
        }
        if (lane == 0) { red[warp] = sum; red[16 + warp] = sq; }
    }

    // ============ 2. prep (style regs arrived long ago) ====================
    {
        st[ 0 * 512 + tid] = a0.x;  st[ 1 * 512 + tid] = a0.y;
        st[ 2 * 512 + tid] = a0.z;  st[ 3 * 512 + tid] = a0.w;
        st[ 4 * 512 + tid] = a1.x;  st[ 5 * 512 + tid] = a1.y;
        st[ 6 * 512 + tid] = a1.z;  st[ 7 * 512 + tid] = a1.w;
        st[ 8 * 512 + tid] = a2.x;  st[ 9 * 512 + tid] = a2.y;
        st[10 * 512 + tid] = a2.z;  st[11 * 512 + tid] = a2.w;
        st[12 * 512 + tid] = a3.x;  st[13 * 512 + tid] = a3.y;
        st[14 * 512 + tid] = a3.z;  st[15 * 512 + tid] = a3.w;
        float tot = a0.x + a0.y + a0.z + a0.w + a1.x + a1.y + a1.z + a1.w
                  + a2.x + a2.y + a2.z + a2.w + a3.x + a3.y + a3.z + a3.w;
        sd[tid] = tot * (1.f / 16.f);
    }
    __syncthreads();

    // d: warp-per-output (o = warp + 16*k); stride-1 smem reads per lane
    {
        const float4* w4base = (const float4*)dw_w;
        #pragma unroll
        for (int k = 0; k < 5; k++) {
            int o = warp + 16 * k;
            if (o < 72) {
                int j = o / 9, pos = o % 9;
                int ky = pos / 3, kx = pos % 3;
                const float* p00 = st + (ky * 4 + kx) * 512;
                const float* p01 = st + (ky * 4 + kx + 1) * 512;
                const float* p10 = st + (ky * 4 + kx + 4) * 512;
                const float* p11 = st + (ky * 4 + kx + 5) * 512;
                float acc = 0.f;
                #pragma unroll
                for (int k16 = 0; k16 < 16; k16++) {
                    int c2 = lane + 32 * k16;
                    float4 w = w4base[j * 512 + c2];
                    acc += w.x * p00[c2] + w.y * p01[c2]
                         + w.z * p10[c2] + w.w * p11[c2];
                }
                #pragma unroll
                for (int off = 16; off; off >>= 1)
                    acc += __shfl_down_sync(0xffffffffu, acc, off);
                if (lane == 0) {
                    float v = acc + dw_b[j];
                    fd[o] = v >= 0.f ? v : 0.01f * v;
                }
            }
        }
    }
    // bias (warps 0-7) and S (warp 8)
    if (warp < 8) {
        const float* row = pb_w + (size_t)(g * 8 + warp) * 512;
        float acc = 0.f;
        #pragma unroll
        for (int k = 0; k < 16; k++) {
            int c2 = lane + 32 * k;
            acc += row[c2] * sd[c2];
        }
        #pragma unroll
        for (int off = 16; off; off >>= 1)
            acc += __shfl_down_sync(0xffffffffu, acc, off);
        if (lane == 0) fb[warp] = acc + pb_b[g * 8 + warp];
    } else if (warp == 8) {
        float acc = 0.f;
        #pragma unroll
        for (int k = 0; k < 16; k++) {
            int c2 = lane + 32 * k;
            float ws = 0.f;
            #pragma unroll
            for (int j = 0; j < 8; j++) ws += pk_w[j * 512 + c2];
            acc += sd[c2] * ws;
        }
        #pragma unroll
        for (int off = 16; off; off >>= 1)
            acc += __shfl_down_sync(0xffffffffu, acc, off);
        if (lane == 0) {
            float bsum = 0.f;
            #pragma unroll
            for (int j = 0; j < 8; j++) bsum += pk_b[j];
            fS_sh = acc + bsum;
        }
    }

    // ============ 3. stats finalize ========================================
    __syncthreads();
    if (tid < 8) {
        float S = red[2 * tid] + red[2 * tid + 1];
        float Q = red[16 + 2 * tid] + red[16 + 2 * tid + 1];
        float mean = S * (1.f / HW);
        float var  = (Q - S * S * (1.f / HW)) * (1.f / (HW - 1));  // ddof=1
        fm[tid] = mean;
        fr[tid] = rsqrtf(var + 1e-5f);
    }
    __syncthreads();

    // ============ conv: 2 rows x 4 cols per thread =========================
    int r2 = tid >> 4;                    // 0..31
    int q4 = (tid & 15) * 4;              // output col base
    int h0 = 2 * r2;                      // output rows h0, h0+1

    float D0[4] = {0.f, 0.f, 0.f, 0.f};
    float D1[4] = {0.f, 0.f, 0.f, 0.f};

    #pragma unroll
    for (int j = 0; j < 8; j++) {
        const float* sj = s + j * CHT;
        const float* fj = fd + j * 9;
        #pragma unroll
        for (int rr = 0; rr < 4; rr++) {
            const float* rp = sj + (h0 + rr) * SCOLS + q4;
            float vL = rp[3];
            float4 f4 = *(const float4*)(rp + 4);   // aligned LDS.128
            float vR = rp[8];
            if (rr < 3) {
                float a = fj[rr * 3], b2 = fj[rr * 3 + 1], cc = fj[rr * 3 + 2];
                D0[0] += a * vL   + b2 * f4.x + cc * f4.y;
                D0[1] += a * f4.x + b2 * f4.y + cc * f4.z;
                D0[2] += a * f4.y + b2 * f4.z + cc * f4.w;
                D0[3] += a * f4.z + b2 * f4.w + cc * vR;
            }
            if (rr >= 1) {
                int kr = rr - 1;
                float a = fj[kr * 3], b2 = fj[kr * 3 + 1], cc = fj[kr * 3 + 2];
                D1[0] += a * vL   + b2 * f4.x + cc * f4.y;
                D1[1] += a * f4.x + b2 * f4.y + cc * f4.z;
                D1[2] += a * f4.y + b2 * f4.z + cc * f4.w;
                D1[3] += a * f4.z + b2 * f4.w + cc * vR;
            }
        }
    }

    float S = fS_sh;
    float* obase = out + (size_t)cbase * HW + h0 * W + q4;

    #pragma unroll
    for (int o = 0; o < 8; o++) {
        const float* so = s + o * CHT;
        float mo = fm[o], ro = fr[o], bo = fb[o];
        float4 r0v, r1v;
        {
            float4 cen = *(const float4*)(so + (h0 + 1) * SCOLS + 4 + q4);
            float p0 = D0[0] * S + bo, p1 = D0[1] * S + bo;
            float p2 = D0[2] * S + bo, p3 = D0[3] * S + bo;
            p0 = p0 >= 0.f ? p0 : 0.01f * p0;
            p1 = p1 >= 0.f ? p1 : 0.01f * p1;
            p2 = p2 >= 0.f ? p2 : 0.01f * p2;
            p3 = p3 >= 0.f ? p3 : 0.01f * p3;
            r0v.x = (cen.x - mo) * ro * p0;
            r0v.y = (cen.y - mo) * ro * p1;
            r0v.z = (cen.z - mo) * ro * p2;
            r0v.w = (cen.w - mo) * ro * p3;
        }
        {
            float4 cen = *(const float4*)(so + (h0 + 2) * SCOLS + 4 + q4);
            float p0 = D1[0] * S + bo, p1 = D1[1] * S + bo;
            float p2 = D1[2] * S + bo, p3 = D1[3] * S + bo;
            p0 = p0 >= 0.f ? p0 : 0.01f * p0;
            p1 = p1 >= 0.f ? p1 : 0.01f * p1;
            p2 = p2 >= 0.f ? p2 : 0.01f * p2;
            p3 = p3 >= 0.f ? p3 : 0.01f * p3;
            r1v.x = (cen.x - mo) * ro * p0;
            r1v.y = (cen.y - mo) * ro * p1;
            r1v.z = (cen.z - mo) * ro * p2;
            r1v.w = (cen.w - mo) * ro * p3;
        }
        __stcs((float4*)(obase + (size_t)o * HW),     r0v);
        __stcs((float4*)(obase + (size_t)o * HW + W), r1v);
    }
}

// ===========================================================================
extern "C" void kernel_launch(void* const* d_in, const int* in_sizes, int n_in,
                              void* d_out, int out_size)
{
    const float* style   = (const float*)d_in[0];
    const float* content = (const float*)d_in[1];
    const float* dw_w    = (const float*)d_in[2];
    const float* dw_b    = (const float*)d_in[3];
    const float* pk_w    = (const float*)d_in[4];
    const float* pk_b    = (const float*)d_in[5];
    const float* pb_w    = (const float*)d_in[6];
    const float* pb_b    = (const float*)d_in[7];
    float* out = (float*)d_out;

    static bool attr_set = false;
    if (!attr_set) {
        cudaFuncSetAttribute(fused_kernel,
                             cudaFuncAttributeMaxDynamicSharedMemorySize,
                             STILE * sizeof(float));
        attr_set = true;
    }

    fused_kernel<<<dim3(NG, N_SAMP), 512, STILE * sizeof(float)>>>(
        content, style, dw_w, dw_b, pk_w, pk_b, pb_w, pb_b, out);
}

// round 13
// speedup vs baseline: 3.4542x; 1.2075x over previous
#include <cuda_runtime.h>
#include <cstdint>
#include <math.h>

#define CH 512
#define NG 64
#define N_SAMP 16
#define H 64
#define W 64
#define HW 4096

#define SROWS 66
#define SCOLS 72                          // interior at col 4 -> 16B-aligned
#define CHT   (SROWS * SCOLS)             // 4752 floats
#define STILE (8 * CHT)                   // 38016 floats = 152064 B

// ===========================================================================
// ONE fused kernel. Grid (64, 16) x 512 threads, 1 CTA/SM (148KB smem).
//  0. style LDG early
//  1. content tile load (batched LDG.128), stats in regs; style -> st smem
//  2. prep: d via thread-per-(j, 8-channel chunk), 9 reg accumulators;
//     bias/S dots
//  3. finalize; conv + pointwise collapse + norm + multiply
// ===========================================================================
__global__ void __launch_bounds__(512, 1) fused_kernel(
    const float* __restrict__ content,
    const float* __restrict__ style,
    const float* __restrict__ dw_w,
    const float* __restrict__ dw_b,
    const float* __restrict__ pk_w,
    const float* __restrict__ pk_b,
    const float* __restrict__ pb_w,
    const float* __restrict__ pb_b,
    float* __restrict__ out)
{
    extern __shared__ float s[];          // [8][SROWS][SCOLS] content tile
    __shared__ float st[16 * 512];        // style TRANSPOSED [pos][channel]
    __shared__ float sd[512];             // style spatial mean
    __shared__ float dredW[16 * 9];       // per-warp d partials
    __shared__ float fd[72];
    __shared__ float fb[8], fm[8], fr[8];
    __shared__ float red[32];
    __shared__ float fS_sh;

    int g = blockIdx.x;
    int n = blockIdx.y;
    int tid = threadIdx.x;
    int lane = tid & 31, warp = tid >> 5;
    int cbase = n * 512 + g * 8;

    // ============ 0. style LDG early =======================================
    const float4* sp = (const float4*)(style + (size_t)(n * 512 + tid) * 16);
    float4 a0 = sp[0], a1 = sp[1], a2 = sp[2], a3 = sp[3];

    // ============ 1. content tile load, stats in regs ======================
    int c    = warp >> 1;
    int half = warp & 1;
    float sum = 0.f, sq = 0.f;
    {
        const float* bc = content + (size_t)(cbase + c) * HW;
        float* sc = s + c * CHT;
        int sub = lane >> 4, q = lane & 15;

        #pragma unroll
        for (int b = 0; b < 4; b++) {
            int lr0 = half * 33 + (8 * b + sub);
            int lr1 = lr0 + 2, lr2 = lr0 + 4, lr3 = lr0 + 6;
            int gr0 = (lr0 == 0) ? 1 : (lr0 == 65 ? 62 : lr0 - 1);
            int gr1 = (lr1 == 0) ? 1 : (lr1 == 65 ? 62 : lr1 - 1);
            int gr2 = (lr2 == 0) ? 1 : (lr2 == 65 ? 62 : lr2 - 1);
            int gr3 = (lr3 == 0) ? 1 : (lr3 == 65 ? 62 : lr3 - 1);
            float4 v0 = *(const float4*)(bc + gr0 * W + 4 * q);
            float4 v1 = *(const float4*)(bc + gr1 * W + 4 * q);
            float4 v2 = *(const float4*)(bc + gr2 * W + 4 * q);
            float4 v3 = *(const float4*)(bc + gr3 * W + 4 * q);
            *(float4*)(sc + lr0 * SCOLS + 4 + 4 * q) = v0;
            *(float4*)(sc + lr1 * SCOLS + 4 + 4 * q) = v1;
            *(float4*)(sc + lr2 * SCOLS + 4 + 4 * q) = v2;
            *(float4*)(sc + lr3 * SCOLS + 4 + 4 * q) = v3;
            if (lr0 >= 1 && lr0 <= 64) {
                sum += v0.x + v0.y + v0.z + v0.w;
                sq  += v0.x * v0.x + v0.y * v0.y + v0.z * v0.z + v0.w * v0.w;
            }
            sum += v1.x + v1.y + v1.z + v1.w;       // lr1..lr3 always interior
            sq  += v1.x * v1.x + v1.y * v1.y + v1.z * v1.z + v1.w * v1.w;
            sum += v2.x + v2.y + v2.z + v2.w;
            sq  += v2.x * v2.x + v2.y * v2.y + v2.z * v2.z + v2.w * v2.w;
            sum += v3.x + v3.y + v3.z + v3.w;
            sq  += v3.x * v3.x + v3.y * v3.y + v3.z * v3.z + v3.w * v3.w;
        }
        if (sub == 0) {                              // tail row (rr = 32)
            int lr = half * 33 + 32;
            int gr = (lr == 65) ? 62 : lr - 1;
            float4 v = *(const float4*)(bc + gr * W + 4 * q);
            *(float4*)(sc + lr * SCOLS + 4 + 4 * q) = v;
            if (lr <= 64) {
                sum += v.x + v.y + v.z + v.w;
                sq  += v.x * v.x + v.y * v.y + v.z * v.z + v.w * v.w;
            }
        }
        // halo columns
        for (int idx = tid; idx < 8 * SROWS; idx += 512) {
            int c2 = idx / SROWS, lr = idx % SROWS;
            int gr = (lr == 0) ? 1 : (lr == 65 ? 62 : lr - 1);
            const float* b2 = content + (size_t)(cbase + c2) * HW + gr * W;
            float* row = s + c2 * CHT + lr * SCOLS;
            row[3]  = b2[1];
            row[68] = b2[62];
        }
        #pragma unroll
        for (int off = 16; off; off >>= 1) {
            sum += __shfl_down_sync(0xffffffffu, sum, off);
            sq  += __shfl_down_sync(0xffffffffu, sq,  off);
        }
        if (lane == 0) { red[warp] = sum; red[16 + warp] = sq; }
    }

    // ---- style -> transposed smem + sd (style regs arrived long ago) ----
    {
        st[ 0 * 512 + tid] = a0.x;  st[ 1 * 512 + tid] = a0.y;
        st[ 2 * 512 + tid] = a0.z;  st[ 3 * 512 + tid] = a0.w;
        st[ 4 * 512 + tid] = a1.x;  st[ 5 * 512 + tid] = a1.y;
        st[ 6 * 512 + tid] = a1.z;  st[ 7 * 512 + tid] = a1.w;
        st[ 8 * 512 + tid] = a2.x;  st[ 9 * 512 + tid] = a2.y;
        st[10 * 512 + tid] = a2.z;  st[11 * 512 + tid] = a2.w;
        st[12 * 512 + tid] = a3.x;  st[13 * 512 + tid] = a3.y;
        st[14 * 512 + tid] = a3.z;  st[15 * 512 + tid] = a3.w;
        float tot = a0.x + a0.y + a0.z + a0.w + a1.x + a1.y + a1.z + a1.w
                  + a2.x + a2.y + a2.z + a2.w + a3.x + a3.y + a3.z + a3.w;
        sd[tid] = tot * (1.f / 16.f);
    }
    __syncthreads();

    // ============ 2. prep ==================================================
    // d-dot: thread = (j = tid>>6, chunk = tid&63); channels c = chunk + 64*i
    {
        int j  = tid >> 6;
        int cc = tid & 63;
        const float4* w4base = (const float4*)dw_w;
        float acc[9];
        #pragma unroll
        for (int i = 0; i < 9; i++) acc[i] = 0.f;

        #pragma unroll
        for (int i = 0; i < 8; i++) {
            int ch = cc + 64 * i;
            float4 w = w4base[j * 512 + ch];
            float stv[16];
            #pragma unroll
            for (int p = 0; p < 16; p++) stv[p] = st[p * 512 + ch];
            #pragma unroll
            for (int ky = 0; ky < 3; ky++)
                #pragma unroll
                for (int kx = 0; kx < 3; kx++)
                    acc[ky * 3 + kx] += w.x * stv[ky * 4 + kx]
                                      + w.y * stv[ky * 4 + kx + 1]
                                      + w.z * stv[ky * 4 + kx + 4]
                                      + w.w * stv[ky * 4 + kx + 5];
        }
        #pragma unroll
        for (int i = 0; i < 9; i++) {
            #pragma unroll
            for (int off = 16; off; off >>= 1)
                acc[i] += __shfl_xor_sync(0xffffffffu, acc[i], off);
        }
        if (lane == 0) {
            #pragma unroll
            for (int i = 0; i < 9; i++) dredW[warp * 9 + i] = acc[i];
        }
    }
    // bias (warps 0-7) and S (warp 8)
    if (warp < 8) {
        const float* row = pb_w + (size_t)(g * 8 + warp) * 512;
        float acc = 0.f;
        #pragma unroll
        for (int k = 0; k < 16; k++) {
            int c2 = lane + 32 * k;
            acc += row[c2] * sd[c2];
        }
        #pragma unroll
        for (int off = 16; off; off >>= 1)
            acc += __shfl_down_sync(0xffffffffu, acc, off);
        if (lane == 0) fb[warp] = acc + pb_b[g * 8 + warp];
    } else if (warp == 8) {
        const float4* pkw4 = (const float4*)pk_w;
        const float4* sd4  = (const float4*)sd;
        float4 sv0 = sd4[lane], sv1 = sd4[lane + 32];
        float4 sv2 = sd4[lane + 64], sv3 = sd4[lane + 96];
        float acc = 0.f;
        #pragma unroll
        for (int j = 0; j < 8; j++) {
            float4 w0 = pkw4[j * 128 + lane];
            float4 w1 = pkw4[j * 128 + lane + 32];
            float4 w2 = pkw4[j * 128 + lane + 64];
            float4 w3 = pkw4[j * 128 + lane + 96];
            acc += w0.x * sv0.x + w0.y * sv0.y + w0.z * sv0.z + w0.w * sv0.w
                 + w1.x * sv1.x + w1.y * sv1.y + w1.z * sv1.z + w1.w * sv1.w
                 + w2.x * sv2.x + w2.y * sv2.y + w2.z * sv2.z + w2.w * sv2.w
                 + w3.x * sv3.x + w3.y * sv3.y + w3.z * sv3.z + w3.w * sv3.w;
        }
        #pragma unroll
        for (int off = 16; off; off >>= 1)
            acc += __shfl_down_sync(0xffffffffu, acc, off);
        if (lane == 0) {
            float bsum = 0.f;
            #pragma unroll
            for (int j = 0; j < 8; j++) bsum += pk_b[j];
            fS_sh = acc + bsum;
        }
    }
    __syncthreads();

    // ============ 3. finalize ==============================================
    if (tid < 72) {
        int j = tid / 9, pos = tid % 9;
        float v = dredW[(2 * j) * 9 + pos] + dredW[(2 * j + 1) * 9 + pos]
                + dw_b[j];
        fd[tid] = v >= 0.f ? v : 0.01f * v;          // leaky
    }
    if (tid >= 96 && tid < 104) {
        int o = tid - 96;
        float S = red[2 * o] + red[2 * o + 1];
        float Q = red[16 + 2 * o] + red[16 + 2 * o + 1];
        float mean = S * (1.f / HW);
        float var  = (Q - S * S * (1.f / HW)) * (1.f / (HW - 1));  // ddof=1
        fm[o] = mean;
        fr[o] = rsqrtf(var + 1e-5f);
    }
    __syncthreads();

    // ============ conv: 2 rows x 4 cols per thread =========================
    int r2 = tid >> 4;                    // 0..31
    int q4 = (tid & 15) * 4;              // output col base
    int h0 = 2 * r2;                      // output rows h0, h0+1

    float D0[4] = {0.f, 0.f, 0.f, 0.f};
    float D1[4] = {0.f, 0.f, 0.f, 0.f};

    #pragma unroll
    for (int j = 0; j < 8; j++) {
        const float* sj = s + j * CHT;
        const float* fj = fd + j * 9;
        #pragma unroll
        for (int rr = 0; rr < 4; rr++) {
            const float* rp = sj + (h0 + rr) * SCOLS + q4;
            float vL = rp[3];
            float4 f4 = *(const float4*)(rp + 4);   // aligned LDS.128
            float vR = rp[8];
            if (rr < 3) {
                float a = fj[rr * 3], b2 = fj[rr * 3 + 1], cc2 = fj[rr * 3 + 2];
                D0[0] += a * vL   + b2 * f4.x + cc2 * f4.y;
                D0[1] += a * f4.x + b2 * f4.y + cc2 * f4.z;
                D0[2] += a * f4.y + b2 * f4.z + cc2 * f4.w;
                D0[3] += a * f4.z + b2 * f4.w + cc2 * vR;
            }
            if (rr >= 1) {
                int kr = rr - 1;
                float a = fj[kr * 3], b2 = fj[kr * 3 + 1], cc2 = fj[kr * 3 + 2];
                D1[0] += a * vL   + b2 * f4.x + cc2 * f4.y;
                D1[1] += a * f4.x + b2 * f4.y + cc2 * f4.z;
                D1[2] += a * f4.y + b2 * f4.z + cc2 * f4.w;
                D1[3] += a * f4.z + b2 * f4.w + cc2 * vR;
            }
        }
    }

    float S = fS_sh;
    float* obase = out + (size_t)cbase * HW + h0 * W + q4;

    #pragma unroll
    for (int o = 0; o < 8; o++) {
        const float* so = s + o * CHT;
        float mo = fm[o], ro = fr[o], bo = fb[o];
        float4 r0v, r1v;
        {
            float4 cen = *(const float4*)(so + (h0 + 1) * SCOLS + 4 + q4);
            float p0 = D0[0] * S + bo, p1 = D0[1] * S + bo;
            float p2 = D0[2] * S + bo, p3 = D0[3] * S + bo;
            p0 = p0 >= 0.f ? p0 : 0.01f * p0;
            p1 = p1 >= 0.f ? p1 : 0.01f * p1;
            p2 = p2 >= 0.f ? p2 : 0.01f * p2;
            p3 = p3 >= 0.f ? p3 : 0.01f * p3;
            r0v.x = (cen.x - mo) * ro * p0;
            r0v.y = (cen.y - mo) * ro * p1;
            r0v.z = (cen.z - mo) * ro * p2;
            r0v.w = (cen.w - mo) * ro * p3;
        }
        {
            float4 cen = *(const float4*)(so + (h0 + 2) * SCOLS + 4 + q4);
            float p0 = D1[0] * S + bo, p1 = D1[1] * S + bo;
            float p2 = D1[2] * S + bo, p3 = D1[3] * S + bo;
            p0 = p0 >= 0.f ? p0 : 0.01f * p0;
            p1 = p1 >= 0.f ? p1 : 0.01f * p1;
            p2 = p2 >= 0.f ? p2 : 0.01f * p2;
            p3 = p3 >= 0.f ? p3 : 0.01f * p3;
            r1v.x = (cen.x - mo) * ro * p0;
            r1v.y = (cen.y - mo) * ro * p1;
            r1v.z = (cen.z - mo) * ro * p2;
            r1v.w = (cen.w - mo) * ro * p3;
        }
        __stcs((float4*)(obase + (size_t)o * HW),     r0v);
        __stcs((float4*)(obase + (size_t)o * HW + W), r1v);
    }
}

// ===========================================================================
extern "C" void kernel_launch(void* const* d_in, const int* in_sizes, int n_in,
                              void* d_out, int out_size)
{
    const float* style   = (const float*)d_in[0];
    const float* content = (const float*)d_in[1];
    const float* dw_w    = (const float*)d_in[2];
    const float* dw_b    = (const float*)d_in[3];
    const float* pk_w    = (const float*)d_in[4];
    const float* pk_b    = (const float*)d_in[5];
    const float* pb_w    = (const float*)d_in[6];
    const float* pb_b    = (const float*)d_in[7];
    float* out = (float*)d_out;

    static bool attr_set = false;
    if (!attr_set) {
        cudaFuncSetAttribute(fused_kernel,
                             cudaFuncAttributeMaxDynamicSharedMemorySize,
                             STILE * sizeof(float));
        attr_set = true;
    }

    fused_kernel<<<dim3(NG, N_SAMP), 512, STILE * sizeof(float)>>>(
        content, style, dw_w, dw_b, pk_w, pk_b, pb_w, pb_b, out);
}